// round 14
// baseline (speedup 1.0000x reference)
#include <cuda_runtime.h>
#include <cuda_fp16.h>
#include <cstddef>
#include <cstdint>

#define N_VARS   4096
#define WIDTH    8192
#define N_LAYERS 12
#define BATCH    1024
#define THREADS  1024
#define BCH      8
#define NPT      (WIDTH / THREADS)          // 8
#define NPRE     4
#define N_PAIRS  (N_LAYERS / 2)             // 6 fused stages
#define HALF_N   4096
#define S_BASE   131072u                    // scratch region byte offset (128KB)

typedef unsigned int u32;

// Fused tables with BAKED BYTE OFFSETS into the rotating smem regions.
// Region schedule: stage p writes H1 (nodes 0..4095) at A_p = (p&1)?0:S_BASE,
// H2 (nodes 4096..8191) in place at node*16. Stage p reads stage p-1 outputs:
// child c<4096 at A_{p-1}+c*16, else c*16. Stage 0 reads leaves at c*16.
__device__ int4 g_fused[N_PAIRS * WIDTH];

__global__ __launch_bounds__(256) void prep_kernel(const int2* __restrict__ children)
{
    const int idx = blockIdx.x * blockDim.x + threadIdx.x;
    const int p = idx >> 13;
    const int i = idx & (WIDTH - 1);
    const int2* ch_even = children + (size_t)(2 * p) * WIDTH;
    const int2 s = __ldg(&children[(size_t)(2 * p + 1) * WIDTH + i]);
    const int2 a = __ldg(&ch_even[s.x]);
    const int2 b = __ldg(&ch_even[s.y]);

    const u32 h1base = (p == 0) ? 0u : (((p - 1) & 1) ? 0u : S_BASE);
    int4 t;
    t.x = (a.x < HALF_N ? h1base : 0u) + (u32)a.x * 16u;
    t.y = (a.y < HALF_N ? h1base : 0u) + (u32)a.y * 16u;
    t.z = (b.x < HALF_N ? h1base : 0u) + (u32)b.x * 16u;
    t.w = (b.y < HALF_N ? h1base : 0u) + (u32)b.y * 16u;
    g_fused[idx] = t;
}

__device__ __forceinline__ u32 h2_as_u32(__half2 h) { u32 r; __builtin_memcpy(&r, &h, 4); return r; }
__device__ __forceinline__ __half2 u32_as_h2(u32 u) { __half2 h; __builtin_memcpy(&h, &u, 4); return h; }
__device__ __forceinline__ u32 fuse_u(u32 x1, u32 y1, u32 x2, u32 y2) {
    return h2_as_u32(__hfma2(u32_as_h2(x2), u32_as_h2(y2),
                             __hmul2(u32_as_h2(x1), u32_as_h2(y1))));
}
__device__ __forceinline__ uint4 gather_fuse(const char* __restrict__ sm, int4 t) {
    const uint4 x1 = *(const uint4*)(sm + t.x);
    const uint4 y1 = *(const uint4*)(sm + t.y);
    const uint4 x2 = *(const uint4*)(sm + t.z);
    const uint4 y2 = *(const uint4*)(sm + t.w);
    return make_uint4(fuse_u(x1.x, y1.x, x2.x, y2.x),
                      fuse_u(x1.y, y1.y, x2.y, y2.y),
                      fuse_u(x1.z, y1.z, x2.z, y2.z),
                      fuse_u(x1.w, y1.w, x2.w, y2.w));
}
#define GETJ(f4, j) ((j) == 0 ? (f4).x : (j) == 1 ? (f4).y : (j) == 2 ? (f4).z : (f4).w)

// One CTA (32 warps) per 8 batch rows. vals node-major (8 halves = 16B/node).
// SMEM: buf 128KB + scratch 64KB. Each stage overlaps the H1 half of its
// stores with the gather phase (write-to-dead-region rotation); only the H2
// half is register-staged across bar1. Tables carry absolute byte offsets.
__global__ __launch_bounds__(THREADS, 1) void wmc_kernel(
    const float* __restrict__ weights,
    float* __restrict__ out)
{
    extern __shared__ char sm[];            // [192 KB]
    __shared__ float wsum[(THREADS / 32) * BCH];

    const int g   = blockIdx.x;
    const int tid = threadIdx.x;

    int4 t_pre[NPRE];
    #pragma unroll
    for (int k = 0; k < NPRE; ++k)
        t_pre[k] = __ldg(&g_fused[tid + k * THREADS]);

    // ---- Load phase: float4 LDG, neg derived in regs, fp16 pack ----
    // thread handles vars 4*tid .. 4*tid+3 for all 8 rows
    {
        const float* wb = weights + (size_t)g * BCH * N_VARS;
        float4 w[8];
        #pragma unroll
        for (int b = 0; b < 8; ++b)
            w[b] = __ldg((const float4*)(wb + (size_t)b * N_VARS) + tid);

        uint4* buf = (uint4*)sm;
        #pragma unroll
        for (int j = 0; j < 4; ++j) {
            const int v = 4 * tid + j;
            __half2 a01 = __floats2half2_rn(GETJ(w[0], j), GETJ(w[1], j));
            __half2 a23 = __floats2half2_rn(GETJ(w[2], j), GETJ(w[3], j));
            __half2 a45 = __floats2half2_rn(GETJ(w[4], j), GETJ(w[5], j));
            __half2 a67 = __floats2half2_rn(GETJ(w[6], j), GETJ(w[7], j));
            buf[v] = make_uint4(h2_as_u32(a01), h2_as_u32(a23),
                                h2_as_u32(a45), h2_as_u32(a67));
            __half2 n01 = __floats2half2_rn(1.0f - GETJ(w[0], j), 1.0f - GETJ(w[1], j));
            __half2 n23 = __floats2half2_rn(1.0f - GETJ(w[2], j), 1.0f - GETJ(w[3], j));
            __half2 n45 = __floats2half2_rn(1.0f - GETJ(w[4], j), 1.0f - GETJ(w[5], j));
            __half2 n67 = __floats2half2_rn(1.0f - GETJ(w[6], j), 1.0f - GETJ(w[7], j));
            buf[v + N_VARS] = make_uint4(h2_as_u32(n01), h2_as_u32(n23),
                                         h2_as_u32(n45), h2_as_u32(n67));
        }
    }
    __syncthreads();

    // ---- Stages 0..4 ----
    #pragma unroll
    for (int p = 0; p < N_PAIRS - 1; ++p) {
        const int4* __restrict__ ft  = g_fused + (size_t)p * WIDTH;
        const int4* __restrict__ ftn = g_fused + (size_t)(p + 1) * WIDTH;
        const u32 Ap = (p & 1) ? 0u : S_BASE;   // H1 destination this stage
        uint4 r[NPT - NPRE];

        // H1: nodes 0..4095 — gather and store immediately to the dead region
        #pragma unroll
        for (int k = 0; k < NPRE; ++k) {
            const uint4 v = gather_fuse(sm, t_pre[k]);
            *(uint4*)(sm + Ap + (u32)(tid + k * THREADS) * 16u) = v;
        }
        // H2: nodes 4096..8191 — gather into registers
        #pragma unroll
        for (int k = NPRE; k < NPT; ++k)
            r[k - NPRE] = gather_fuse(sm, __ldg(&ft[tid + k * THREADS]));

        __syncthreads();                    // all gathers done
        #pragma unroll
        for (int k = NPRE; k < NPT; ++k)
            *(uint4*)(sm + (u32)(tid + k * THREADS) * 16u) = r[k - NPRE];
        #pragma unroll
        for (int k = 0; k < NPRE; ++k)
            t_pre[k] = __ldg(&ftn[tid + k * THREADS]);
        __syncthreads();                    // H2 stores visible
    }

    // ---- Stage 5 (layers 10+11): fold into fp32 reduction ----
    float acc[BCH];
    #pragma unroll
    for (int j = 0; j < BCH; ++j) acc[j] = 0.0f;
    {
        const int4* __restrict__ ft = g_fused + (size_t)(N_PAIRS - 1) * WIDTH;
        #pragma unroll
        for (int k = 0; k < NPT; ++k) {
            const int4 t = (k < NPRE) ? t_pre[k] : __ldg(&ft[tid + k * THREADS]);
            const uint4 rv = gather_fuse(sm, t);
            const u32 rs[4] = {rv.x, rv.y, rv.z, rv.w};
            #pragma unroll
            for (int q = 0; q < 4; ++q) {
                float2 f = __half22float2(u32_as_h2(rs[q]));
                acc[2*q + 0] += f.x;
                acc[2*q + 1] += f.y;
            }
        }
    }

    // ---- CTA-wide reduction of 8 fp32 accumulators ----
    #pragma unroll
    for (int o = 16; o > 0; o >>= 1) {
        #pragma unroll
        for (int j = 0; j < BCH; ++j)
            acc[j] += __shfl_xor_sync(0xffffffffu, acc[j], o);
    }
    if ((tid & 31) == 0) {
        #pragma unroll
        for (int j = 0; j < BCH; ++j)
            wsum[(tid >> 5) * BCH + j] = acc[j];
    }
    __syncthreads();

    if (tid < 32) {
        #pragma unroll
        for (int j = 0; j < BCH; ++j) {
            float s = wsum[tid * BCH + j];
            #pragma unroll
            for (int o = 16; o > 0; o >>= 1)
                s += __shfl_xor_sync(0xffffffffu, s, o);
            if (tid == 0) out[g * BCH + j] = s;
        }
    }
}

extern "C" void kernel_launch(void* const* d_in, const int* in_sizes, int n_in,
                              void* d_out, int out_size)
{
    const float* weights  = (const float*)d_in[0];
    const int2*  children = (const int2*)d_in[2];
    float* out = (float*)d_out;

    prep_kernel<<<(N_PAIRS * WIDTH) / 256, 256>>>(children);

    const int smem_bytes = 192 * 1024;      // 128KB buf + 64KB scratch
    cudaFuncSetAttribute(wmc_kernel, cudaFuncAttributeMaxDynamicSharedMemorySize, smem_bytes);
    wmc_kernel<<<BATCH / BCH, THREADS, smem_bytes>>>(weights, out);
}

// round 15
// speedup vs baseline: 1.0376x; 1.0376x over previous
#include <cuda_runtime.h>
#include <cuda_fp16.h>
#include <cstddef>
#include <cstdint>

#define N_VARS   4096
#define WIDTH    8192
#define N_LAYERS 12
#define BATCH    1024
#define THREADS  512
#define BCH      8
#define NPT      (WIDTH / THREADS)          // 16 nodes per thread
#define NH       (NPT / 2)                  // 8 (H1 half)
#define N_PAIRS  (N_LAYERS / 2)             // 6 fused stages
#define HALF_N   4096
#define S_BASE   131072u                    // scratch region byte offset (128KB)

typedef unsigned int u32;

// Fused tables with BAKED BYTE OFFSETS into the rotating smem regions.
// Stage p writes H1 (nodes 0..4095) at A_p=(p&1)?0:S_BASE, H2 in place.
// Stage p reads prev outputs: child c<4096 at A_{p-1}+c*16 else c*16;
// stage 0 reads leaves at c*16.
__device__ int4 g_fused[N_PAIRS * WIDTH];

__global__ __launch_bounds__(256) void prep_kernel(const int2* __restrict__ children)
{
    const int idx = blockIdx.x * blockDim.x + threadIdx.x;
    const int p = idx >> 13;
    const int i = idx & (WIDTH - 1);
    const int2* ch_even = children + (size_t)(2 * p) * WIDTH;
    const int2 s = __ldg(&children[(size_t)(2 * p + 1) * WIDTH + i]);
    const int2 a = __ldg(&ch_even[s.x]);
    const int2 b = __ldg(&ch_even[s.y]);

    const u32 h1base = (p == 0) ? 0u : (((p - 1) & 1) ? 0u : S_BASE);
    int4 t;
    t.x = (a.x < HALF_N ? h1base : 0u) + (u32)a.x * 16u;
    t.y = (a.y < HALF_N ? h1base : 0u) + (u32)a.y * 16u;
    t.z = (b.x < HALF_N ? h1base : 0u) + (u32)b.x * 16u;
    t.w = (b.y < HALF_N ? h1base : 0u) + (u32)b.y * 16u;
    g_fused[idx] = t;
}

__device__ __forceinline__ u32 h2_as_u32(__half2 h) { u32 r; __builtin_memcpy(&r, &h, 4); return r; }
__device__ __forceinline__ __half2 u32_as_h2(u32 u) { __half2 h; __builtin_memcpy(&h, &u, 4); return h; }
__device__ __forceinline__ u32 fuse_u(u32 x1, u32 y1, u32 x2, u32 y2) {
    return h2_as_u32(__hfma2(u32_as_h2(x2), u32_as_h2(y2),
                             __hmul2(u32_as_h2(x1), u32_as_h2(y1))));
}
__device__ __forceinline__ uint4 gather_fuse(const char* __restrict__ sm, int4 t) {
    const uint4 x1 = *(const uint4*)(sm + t.x);
    const uint4 y1 = *(const uint4*)(sm + t.y);
    const uint4 x2 = *(const uint4*)(sm + t.z);
    const uint4 y2 = *(const uint4*)(sm + t.w);
    return make_uint4(fuse_u(x1.x, y1.x, x2.x, y2.x),
                      fuse_u(x1.y, y1.y, x2.y, y2.y),
                      fuse_u(x1.z, y1.z, x2.z, y2.z),
                      fuse_u(x1.w, y1.w, x2.w, y2.w));
}
#define GETJ(f4, j) ((j) == 0 ? (f4).x : (j) == 1 ? (f4).y : (j) == 2 ? (f4).z : (f4).w)

// One CTA (16 warps, 512 threads, <=128 regs) per 8 batch rows.
// vals node-major (8 halves = 16B/node); SMEM buf 128KB + scratch 64KB.
// 16 nodes/thread for deep LDS ILP; ALL 16 next-stage table entries are
// register-prefetched during the store phase -> zero LDG in the gather phase.
// H1 (8 nodes) stored immediately to the rotating dead region; H2 (8 nodes)
// register-staged across bar1.
__global__ __launch_bounds__(THREADS, 1) void wmc_kernel(
    const float* __restrict__ weights,
    float* __restrict__ out)
{
    extern __shared__ char sm[];            // [192 KB]
    __shared__ float wsum[(THREADS / 32) * BCH];

    const int g   = blockIdx.x;
    const int tid = threadIdx.x;

    // ---- Stage-0 table: full register prefetch (16 x int4) ----
    int4 t_pre[NPT];
    #pragma unroll
    for (int k = 0; k < NPT; ++k)
        t_pre[k] = __ldg(&g_fused[tid + k * THREADS]);

    // ---- Load phase: 2x (8 x LDG.128), neg derived in regs, fp16 pack ----
    {
        const float* wb = weights + (size_t)g * BCH * N_VARS;
        uint4* buf = (uint4*)sm;
        #pragma unroll
        for (int h = 0; h < 2; ++h) {
            const int t4 = tid + h * THREADS;   // float4 index within a row
            float4 w[8];
            #pragma unroll
            for (int b = 0; b < 8; ++b)
                w[b] = __ldg((const float4*)(wb + (size_t)b * N_VARS) + t4);
            #pragma unroll
            for (int j = 0; j < 4; ++j) {
                const int v = 4 * t4 + j;
                __half2 a01 = __floats2half2_rn(GETJ(w[0], j), GETJ(w[1], j));
                __half2 a23 = __floats2half2_rn(GETJ(w[2], j), GETJ(w[3], j));
                __half2 a45 = __floats2half2_rn(GETJ(w[4], j), GETJ(w[5], j));
                __half2 a67 = __floats2half2_rn(GETJ(w[6], j), GETJ(w[7], j));
                buf[v] = make_uint4(h2_as_u32(a01), h2_as_u32(a23),
                                    h2_as_u32(a45), h2_as_u32(a67));
                __half2 n01 = __floats2half2_rn(1.0f - GETJ(w[0], j), 1.0f - GETJ(w[1], j));
                __half2 n23 = __floats2half2_rn(1.0f - GETJ(w[2], j), 1.0f - GETJ(w[3], j));
                __half2 n45 = __floats2half2_rn(1.0f - GETJ(w[4], j), 1.0f - GETJ(w[5], j));
                __half2 n67 = __floats2half2_rn(1.0f - GETJ(w[6], j), 1.0f - GETJ(w[7], j));
                buf[v + N_VARS] = make_uint4(h2_as_u32(n01), h2_as_u32(n23),
                                             h2_as_u32(n45), h2_as_u32(n67));
            }
        }
    }
    __syncthreads();

    // ---- Stages 0..4 ----
    #pragma unroll
    for (int p = 0; p < N_PAIRS - 1; ++p) {
        const int4* __restrict__ ftn = g_fused + (size_t)(p + 1) * WIDTH;
        const u32 Ap = (p & 1) ? 0u : S_BASE;   // H1 destination this stage
        uint4 r[NH];

        // H1 (nodes 0..4095): gather + immediate store to the dead region
        #pragma unroll
        for (int k = 0; k < NH; ++k) {
            const uint4 v = gather_fuse(sm, t_pre[k]);
            *(uint4*)(sm + Ap + (u32)(tid + k * THREADS) * 16u) = v;
        }
        // H2 (nodes 4096..8191): gather into registers
        #pragma unroll
        for (int k = NH; k < NPT; ++k)
            r[k - NH] = gather_fuse(sm, t_pre[k]);

        __syncthreads();                    // all gathers done
        #pragma unroll
        for (int k = NH; k < NPT; ++k)
            *(uint4*)(sm + (u32)(tid + k * THREADS) * 16u) = r[k - NH];
        // full next-stage table prefetch: L2 latency drains under bar
        #pragma unroll
        for (int k = 0; k < NPT; ++k)
            t_pre[k] = __ldg(&ftn[tid + k * THREADS]);
        __syncthreads();                    // H2 stores visible
    }

    // ---- Stage 5 (layers 10+11): fold into fp32 reduction ----
    float acc[BCH];
    #pragma unroll
    for (int j = 0; j < BCH; ++j) acc[j] = 0.0f;
    #pragma unroll
    for (int k = 0; k < NPT; ++k) {
        const uint4 rv = gather_fuse(sm, t_pre[k]);
        const u32 rs[4] = {rv.x, rv.y, rv.z, rv.w};
        #pragma unroll
        for (int q = 0; q < 4; ++q) {
            float2 f = __half22float2(u32_as_h2(rs[q]));
            acc[2*q + 0] += f.x;
            acc[2*q + 1] += f.y;
        }
    }

    // ---- CTA-wide reduction of 8 fp32 accumulators ----
    #pragma unroll
    for (int o = 16; o > 0; o >>= 1) {
        #pragma unroll
        for (int j = 0; j < BCH; ++j)
            acc[j] += __shfl_xor_sync(0xffffffffu, acc[j], o);
    }
    if ((tid & 31) == 0) {
        #pragma unroll
        for (int j = 0; j < BCH; ++j)
            wsum[(tid >> 5) * BCH + j] = acc[j];
    }
    __syncthreads();

    if (tid < 32) {
        #pragma unroll
        for (int j = 0; j < BCH; ++j) {
            float s = (tid < THREADS / 32) ? wsum[tid * BCH + j] : 0.0f;
            #pragma unroll
            for (int o = 8; o > 0; o >>= 1)
                s += __shfl_xor_sync(0xffffffffu, s, o);
            if (tid == 0) out[g * BCH + j] = s;
        }
    }
}

extern "C" void kernel_launch(void* const* d_in, const int* in_sizes, int n_in,
                              void* d_out, int out_size)
{
    const float* weights  = (const float*)d_in[0];
    const int2*  children = (const int2*)d_in[2];
    float* out = (float*)d_out;

    prep_kernel<<<(N_PAIRS * WIDTH) / 256, 256>>>(children);

    const int smem_bytes = 192 * 1024;      // 128KB buf + 64KB scratch
    cudaFuncSetAttribute(wmc_kernel, cudaFuncAttributeMaxDynamicSharedMemorySize, smem_bytes);
    wmc_kernel<<<BATCH / BCH, THREADS, smem_bytes>>>(weights, out);
}